// round 3
// baseline (speedup 1.0000x reference)
#include <cuda_runtime.h>
#include <math.h>

// Problem constants
#define M_TOK   65536      // B*T = 16*4096
#define DIM     128
#define KCODE   1024
#define BM      128        // tokens per block
#define BN      128        // codes per n-tile
#define NTILES  (KCODE/BN) // 8
#define GRID_MAIN (M_TOK/BM) // 512

// Output layout (floats): [z_q | similarity | ids | loss]
#define SIM_OFF  8388608ULL   // 16*4096*128
#define IDS_OFF  75497472ULL  // + 16*4096*1024
#define LOSS_OFF 75563008ULL  // + 65536

// Scratch (__device__ globals; no allocation allowed)
__device__ float g_nz[M_TOK];
__device__ float g_rz[M_TOK];
__device__ float g_ne[KCODE];
__device__ float g_re[KCODE];
__device__ float g_partial[GRID_MAIN];

// ---- packed f32x2 helpers (ptxas never auto-fuses; PTX only) ----
__device__ __forceinline__ unsigned long long pk2(float a, float b) {
    unsigned long long r;
    asm("mov.b64 %0, {%1,%2};" : "=l"(r) : "f"(a), "f"(b));
    return r;
}
__device__ __forceinline__ void upk2(unsigned long long v, float& a, float& b) {
    asm("mov.b64 {%0,%1}, %2;" : "=f"(a), "=f"(b) : "l"(v));
}
__device__ __forceinline__ void fma2(unsigned long long& c, unsigned long long a, unsigned long long b) {
    asm("fma.rn.f32x2 %0, %1, %2, %0;" : "+l"(c) : "l"(a), "l"(b));
}

// ---- row-wise squared norms + rsqrt (warp per row, D=128) ----
__global__ void row_norm_z(const float* __restrict__ x) {
    int row  = blockIdx.x * 8 + (threadIdx.x >> 5);
    int lane = threadIdx.x & 31;
    float4 v = reinterpret_cast<const float4*>(x)[(size_t)row * 32 + lane];
    float s = fmaf(v.x, v.x, fmaf(v.y, v.y, fmaf(v.z, v.z, v.w * v.w)));
#pragma unroll
    for (int m = 16; m; m >>= 1) s += __shfl_xor_sync(0xffffffffu, s, m);
    if (lane == 0) { g_nz[row] = s; g_rz[row] = rsqrtf(s); }
}
__global__ void row_norm_e(const float* __restrict__ x) {
    int row  = blockIdx.x * 8 + (threadIdx.x >> 5);
    int lane = threadIdx.x & 31;
    float4 v = reinterpret_cast<const float4*>(x)[(size_t)row * 32 + lane];
    float s = fmaf(v.x, v.x, fmaf(v.y, v.y, fmaf(v.z, v.z, v.w * v.w)));
#pragma unroll
    for (int m = 16; m; m >>= 1) s += __shfl_xor_sync(0xffffffffu, s, m);
    if (lane == 0) { g_ne[row] = s; g_re[row] = rsqrtf(s); }
}

// Transpose-load a [128 rows x 128 cols] fp32 tile into smem as [d][x] with
// XOR swizzle on the 16B unit index: element (d, r) lives at
//   d*128 + (((r>>2) ^ (d>>2)) << 2) + (r & 3)
// Stores: <=4-way conflicts (cheap, once per tile). Reads: conflict-free LDS.128.
__device__ __forceinline__ void load_tile_T(const float* __restrict__ S, float* __restrict__ dst,
                                            int warp, int lane) {
    const float4* S4 = reinterpret_cast<const float4*>(S);
#pragma unroll
    for (int it = 0; it < 16; ++it) {
        int r = warp * 16 + it;
        float4 v = S4[r * 32 + lane];
#pragma unroll
        for (int j = 0; j < 4; ++j) {
            int d = lane * 4 + j;
            float f = (j == 0) ? v.x : (j == 1) ? v.y : (j == 2) ? v.z : v.w;
            dst[d * 128 + ((((r >> 2) ^ (d >> 2)) & 31) << 2) + (r & 3)] = f;
        }
    }
}

__global__ __launch_bounds__(256, 1)
void vq_main(const float* __restrict__ Z, const float* __restrict__ E, float* __restrict__ out) {
    extern __shared__ float smem[];
    float* As    = smem;                    // 16384 floats (z tile, transposed+swizzled)
    float* Bs    = smem + BM * DIM;         // 16384 floats (E tile, transposed+swizzled)
    float* ne_sm = smem + 2 * BM * DIM;     // 1024
    float* re_sm = ne_sm + KCODE;           // 1024
    int*   ids_sm = (int*)(re_sm + KCODE);  // 128
    float* lt_sm  = (float*)(ids_sm + BM);  // 128

    const int tid  = threadIdx.x;
    const int lane = tid & 31;
    const int warp = tid >> 5;
    const int tx   = tid & 15;   // n-direction
    const int ty   = tid >> 4;   // m-direction
    const int m0   = blockIdx.x * BM;

    float* zq   = out;
    float* sim  = out + SIM_OFF;
    float* idsf = out + IDS_OFF;

    // Preload z tile (once) and full codebook norms into smem
    load_tile_T(Z + (size_t)m0 * DIM, As, warp, lane);
    for (int i = tid; i < KCODE; i += 256) { ne_sm[i] = g_ne[i]; re_sm[i] = g_re[i]; }

    float bestD[8];
    int   bestI[8];
#pragma unroll
    for (int i = 0; i < 8; i++) { bestD[i] = 3.4e38f; bestI[i] = 0; }

    __syncthreads();

    const float4*     As4 = reinterpret_cast<const float4*>(As);
    const ulonglong2* Bs2 = reinterpret_cast<const ulonglong2*>(Bs);

    for (int t = 0; t < NTILES; ++t) {
        if (t) __syncthreads();                      // prev tile reads done before overwrite
        load_tile_T(E + (size_t)t * BN * DIM, Bs, warp, lane);
        __syncthreads();

        unsigned long long acc[8][4];
#pragma unroll
        for (int i = 0; i < 8; i++)
#pragma unroll
            for (int j = 0; j < 4; j++) acc[i][j] = 0ULL;

        // 128-deep dot product, 8(m) x 8(n) per thread, packed f32x2 FMAs
#pragma unroll 4
        for (int d = 0; d < DIM; ++d) {
            int sw = d >> 2;
            float4     a0 = As4[d * 32 + (ty ^ sw)];
            float4     a1 = As4[d * 32 + ((ty + 16) ^ sw)];
            ulonglong2 b0 = Bs2[d * 32 + (tx ^ sw)];
            ulonglong2 b1 = Bs2[d * 32 + ((tx + 16) ^ sw)];
            unsigned long long av[8];
            av[0] = pk2(a0.x, a0.x); av[1] = pk2(a0.y, a0.y);
            av[2] = pk2(a0.z, a0.z); av[3] = pk2(a0.w, a0.w);
            av[4] = pk2(a1.x, a1.x); av[5] = pk2(a1.y, a1.y);
            av[6] = pk2(a1.z, a1.z); av[7] = pk2(a1.w, a1.w);
            unsigned long long bv[4] = { b0.x, b0.y, b1.x, b1.y };
#pragma unroll
            for (int i = 0; i < 8; i++)
#pragma unroll
                for (int j = 0; j < 4; j++) fma2(acc[i][j], av[i], bv[j]);
        }

        // Epilogue: dist/argmin + similarity write
        const int nb = t * BN;
        float ne0[4], ne1[4], re0[4], re1[4];
#pragma unroll
        for (int q = 0; q < 4; q++) {
            ne0[q] = ne_sm[nb + 4 * tx + q];      re0[q] = re_sm[nb + 4 * tx + q];
            ne1[q] = ne_sm[nb + 64 + 4 * tx + q]; re1[q] = re_sm[nb + 64 + 4 * tx + q];
        }
#pragma unroll
        for (int i = 0; i < 8; i++) {
            const int ml = (i < 4) ? (4 * ty + i) : (60 + 4 * ty + i);
            const size_t mg = (size_t)(m0 + ml);
            float pv0[4], pv1[4];
            upk2(acc[i][0], pv0[0], pv0[1]); upk2(acc[i][1], pv0[2], pv0[3]);
            upk2(acc[i][2], pv1[0], pv1[1]); upk2(acc[i][3], pv1[2], pv1[3]);
            const float nzi = g_nz[mg];
            const float rzi = g_rz[mg];
            // argmin update — reference association order: (-2*dot + nz) + ne;
            // strict '<' keeps the first (lowest) index, matching jnp.argmin ties.
#pragma unroll
            for (int q = 0; q < 4; q++) {
                float dd = (-2.f * pv0[q] + nzi) + ne0[q];
                if (dd < bestD[i]) { bestD[i] = dd; bestI[i] = nb + 4 * tx + q; }
            }
#pragma unroll
            for (int q = 0; q < 4; q++) {
                float dd = (-2.f * pv1[q] + nzi) + ne1[q];
                if (dd < bestD[i]) { bestD[i] = dd; bestI[i] = nb + 64 + 4 * tx + q; }
            }
            float4 s0 = make_float4(pv0[0] * rzi * re0[0], pv0[1] * rzi * re0[1],
                                    pv0[2] * rzi * re0[2], pv0[3] * rzi * re0[3]);
            float4 s1 = make_float4(pv1[0] * rzi * re1[0], pv1[1] * rzi * re1[1],
                                    pv1[2] * rzi * re1[2], pv1[3] * rzi * re1[3]);
            reinterpret_cast<float4*>(sim + mg * KCODE + nb + 4 * tx)[0]      = s0;
            reinterpret_cast<float4*>(sim + mg * KCODE + nb + 64 + 4 * tx)[0] = s1;
        }
    }

    // Reduce argmin across the 16 tx-lanes (lanes 0-15 / 16-31 independently)
#pragma unroll
    for (int i = 0; i < 8; i++) {
        float bd = bestD[i]; int bi = bestI[i];
#pragma unroll
        for (int msk = 1; msk < 16; msk <<= 1) {
            float od = __shfl_xor_sync(0xffffffffu, bd, msk);
            int   oi = __shfl_xor_sync(0xffffffffu, bi, msk);
            if (od < bd || (od == bd && oi < bi)) { bd = od; bi = oi; }
        }
        if (tx == 0) {
            const int ml = (i < 4) ? (4 * ty + i) : (60 + 4 * ty + i);
            ids_sm[ml] = bi;
            idsf[m0 + ml] = (float)bi;
            // ||z_e - z_q||^2 == dist_min exactly
            lt_sm[ml] = sqrtf(fmaxf(bd, 0.f));
        }
    }
    __syncthreads();

    // Gather z_q rows from the codebook (E is L2-resident)
    const float4* E4  = reinterpret_cast<const float4*>(E);
    float4*       ZQ4 = reinterpret_cast<float4*>(zq);
#pragma unroll
    for (int r = 0; r < 16; r++) {
        int ml = warp * 16 + r;
        int id = ids_sm[ml];
        ZQ4[(size_t)(m0 + ml) * 32 + lane] = E4[(size_t)id * 32 + lane];
    }

    // Deterministic per-block loss partial (fixed serial order)
    if (tid == 0) {
        float s = 0.f;
        for (int i = 0; i < BM; i++) s += lt_sm[i];
        g_partial[blockIdx.x] = s;
    }
}

// loss = loss_codebook + BETA*loss_commit = 1.25 * mean ||z_e - z_q||
__global__ void loss_final(float* __restrict__ out) {
    float s = 0.f;
    for (int i = 0; i < GRID_MAIN; i++) s += g_partial[i];
    out[LOSS_OFF] = 1.25f * (s * (1.f / 65536.f));
}

extern "C" void kernel_launch(void* const* d_in, const int* in_sizes, int n_in,
                              void* d_out, int out_size) {
    (void)in_sizes; (void)n_in; (void)out_size;
    const float* Z = (const float*)d_in[0];   // z_e            [65536, 128]
    const float* E = (const float*)d_in[1];   // vecs_embedding [1024, 128]
    float* out = (float*)d_out;

    const size_t smem_bytes = (size_t)(2 * BM * DIM + 2 * KCODE) * sizeof(float)
                            + BM * sizeof(int) + BM * sizeof(float);
    cudaFuncSetAttribute((const void*)vq_main,
                         cudaFuncAttributeMaxDynamicSharedMemorySize, (int)smem_bytes);

    row_norm_z<<<M_TOK / 8, 256>>>(Z);
    row_norm_e<<<KCODE / 8, 256>>>(E);
    vq_main<<<GRID_MAIN, 256, smem_bytes>>>(Z, E, out);
    loss_final<<<1, 1>>>(out);
}